// round 1
// baseline (speedup 1.0000x reference)
#include <cuda_runtime.h>
#include <math.h>

// Problem constants
constexpr int cB   = 32;
constexpr int cN   = 256;
constexpr int cF   = 300;
constexpr int cO   = 256;
constexpr int cH   = 8;
constexpr int cHO  = 2048;   // H*O
constexpr int cOUT = 512;
#define NEGV (-9e15f)

// ---------------- scratch (device globals; no allocation) ----------------
__device__ float g_x    [cB * cN * cF];                 // (B*N, F)
__device__ float g_Wh   [(size_t)cH * cB * cN * cO];    // (H,B,N,O)
__device__ float g_e1   [cH * cB * cN];
__device__ float g_e2   [cH * cB * cN];
__device__ float g_attn [(size_t)cH * cB * cN * cN];    // (H,B,N,N)
__device__ float g_hHB  [(size_t)cH * cB * cN * cO];    // (H,B,N,O)
__device__ float g_h1   [(size_t)cB * cN * cHO];        // (B,N,H*O)
__device__ float g_Wh2  [(size_t)cB * cN * cOUT];       // (B,N,OUT)
__device__ float g_e1b  [cB * cN];
__device__ float g_e2b  [cB * cN];
__device__ float g_attn2[(size_t)cB * cN * cN];         // (B,N,N)
__device__ float g_tmp  [(size_t)cB * cN * cOUT];       // pre-ELU output

// ---------------- embedding gather ----------------
__global__ void gather_kernel(const int* __restrict__ fea,
                              const float* __restrict__ embed) {
    int i = blockIdx.x * blockDim.x + threadIdx.x;
    if (i >= cB * cN * cF) return;
    int f  = i % cF;
    int bn = i / cF;
    g_x[i] = embed[(size_t)fea[bn] * cF + f];
}

// ---------------- generic batched GEMM: C = A @ B ----------------
// A: (M,K) row-major, B: (K,Nc) row-major, C: (M,Nc) row-major
// 64x64 block tile, K-tile 16, 256 threads, 4x4 microtile per thread.
__global__ __launch_bounds__(256)
void gemm_kernel(const float* __restrict__ A, const float* __restrict__ Bm,
                 float* __restrict__ C,
                 int M, int Nc, int K,
                 long long sA, long long sB, long long sC) {
    constexpr int BM = 64, BN = 64, BK = 16;
    __shared__ float As[BK][BM + 1];  // +1 pad: conflict-free transposed store
    __shared__ float Bs[BK][BN];

    int batch = blockIdx.z;
    A  += (long long)batch * sA;
    Bm += (long long)batch * sB;
    C  += (long long)batch * sC;

    int m0 = blockIdx.y * BM;
    int n0 = blockIdx.x * BN;
    int t  = threadIdx.x;
    int ty = t >> 4;          // 0..15
    int tx = t & 15;          // 0..15

    float acc[4][4] = {};

    for (int k0 = 0; k0 < K; k0 += BK) {
        // load A tile (64x16) transposed into As
        #pragma unroll
        for (int i = 0; i < 4; i++) {
            int idx = t + i * 256;
            int r = idx >> 4, c = idx & 15;
            float v = 0.f;
            if (k0 + c < K) v = A[(long long)(m0 + r) * K + (k0 + c)];
            As[c][r] = v;
        }
        // load B tile (16x64)
        #pragma unroll
        for (int i = 0; i < 4; i++) {
            int idx = t + i * 256;
            int r = idx >> 6, c = idx & 63;
            float v = 0.f;
            if (k0 + r < K) v = Bm[(long long)(k0 + r) * Nc + (n0 + c)];
            Bs[r][c] = v;
        }
        __syncthreads();

        #pragma unroll
        for (int kk = 0; kk < BK; kk++) {
            float a[4], b[4];
            #pragma unroll
            for (int i = 0; i < 4; i++) a[i] = As[kk][ty * 4 + i];
            #pragma unroll
            for (int j = 0; j < 4; j++) b[j] = Bs[kk][tx * 4 + j];
            #pragma unroll
            for (int i = 0; i < 4; i++)
                #pragma unroll
                for (int j = 0; j < 4; j++)
                    acc[i][j] = fmaf(a[i], b[j], acc[i][j]);
        }
        __syncthreads();
    }

    #pragma unroll
    for (int i = 0; i < 4; i++)
        #pragma unroll
        for (int j = 0; j < 4; j++)
            C[(long long)(m0 + ty * 4 + i) * Nc + (n0 + tx * 4 + j)] = acc[i][j];
}

// ---------------- attention coefficients: e1/e2 dot products ----------------
// One warp per row. Wh row length = Of. head = row / rowsPerHead; a: (heads, 2*Of)
__global__ void attn_coef_kernel(const float* __restrict__ Wh,
                                 const float* __restrict__ a,
                                 float* __restrict__ e1, float* __restrict__ e2,
                                 int Of, int rowsPerHead, int totalRows) {
    int gw = (blockIdx.x * blockDim.x + threadIdx.x) >> 5;
    if (gw >= totalRows) return;
    int lane = threadIdx.x & 31;
    int h = gw / rowsPerHead;
    const float* w  = Wh + (size_t)gw * Of;
    const float* a1 = a + (size_t)h * 2 * Of;
    const float* a2 = a1 + Of;
    float s1 = 0.f, s2 = 0.f;
    for (int o = lane; o < Of; o += 32) {
        float v = w[o];
        s1 = fmaf(v, a1[o], s1);
        s2 = fmaf(v, a2[o], s2);
    }
    #pragma unroll
    for (int off = 16; off; off >>= 1) {
        s1 += __shfl_xor_sync(0xffffffffu, s1, off);
        s2 += __shfl_xor_sync(0xffffffffu, s2, off);
    }
    if (lane == 0) { e1[gw] = s1; e2[gw] = s2; }
}

// ---------------- masked leaky-relu softmax over a row of N=256 ----------------
// One block (256 threads) per row r. Row layout: (H,B,N) (or (B,N) with H=1).
// adj is (B,N,N): b = (r/cN) % cB, n = r % cN.
__global__ void softmax_kernel(const float* __restrict__ e1,
                               const float* __restrict__ e2,
                               const int* __restrict__ adj,
                               float* __restrict__ attn) {
    int r  = blockIdx.x;
    int m  = threadIdx.x;
    int hb = r / cN;
    int n  = r - hb * cN;
    int b  = hb % cB;

    float v = e1[r] + e2[(size_t)hb * cN + m];
    v = v > 0.f ? v : 0.2f * v;                       // leaky relu
    if (adj[((size_t)b * cN + n) * cN + m] <= 0) v = NEGV;

    __shared__ float red[32];
    // --- block max ---
    float t = v;
    #pragma unroll
    for (int off = 16; off; off >>= 1) t = fmaxf(t, __shfl_xor_sync(0xffffffffu, t, off));
    if ((m & 31) == 0) red[m >> 5] = t;
    __syncthreads();
    if (m < 32) {
        float q = (m < 8) ? red[m] : -INFINITY;
        #pragma unroll
        for (int off = 4; off; off >>= 1) q = fmaxf(q, __shfl_xor_sync(0xffffffffu, q, off));
        if (m == 0) red[0] = q;
    }
    __syncthreads();
    float vmax = red[0];

    float ex = expf(v - vmax);

    __syncthreads();
    // --- block sum ---
    t = ex;
    #pragma unroll
    for (int off = 16; off; off >>= 1) t += __shfl_xor_sync(0xffffffffu, t, off);
    if ((m & 31) == 0) red[m >> 5] = t;
    __syncthreads();
    if (m < 32) {
        float q = (m < 8) ? red[m] : 0.f;
        #pragma unroll
        for (int off = 4; off; off >>= 1) q += __shfl_xor_sync(0xffffffffu, q, off);
        if (m == 0) red[0] = q;
    }
    __syncthreads();

    attn[(size_t)r * cN + m] = ex / red[0];
}

// ---------------- head merge: elu + transpose (H,B,N,O)->(B,N,H*O) + mask ----------------
__global__ void head_merge_kernel(const float* __restrict__ mask) {
    int i = blockIdx.x * blockDim.x + threadIdx.x;
    if (i >= cH * cB * cN * cO) return;
    int o   = i & (cO - 1);
    int rem = i >> 8;             // /cO
    int n   = rem & (cN - 1); rem >>= 8;
    int b   = rem & (cB - 1);
    int h   = rem >> 5;           // /cB
    float v = g_hHB[i];
    v = v > 0.f ? v : expm1f(v);  // ELU
    g_h1[((size_t)(b * cN + n)) * cHO + h * cO + o] = v * mask[b * cN + n];
}

// ---------------- final: out = elu(tmp * mask) ----------------
__global__ void final_elu_kernel(const float* __restrict__ mask,
                                 float* __restrict__ out) {
    int i = blockIdx.x * blockDim.x + threadIdx.x;
    if (i >= cB * cN * cOUT) return;
    float v = g_tmp[i] * mask[i / cOUT];
    out[i] = v > 0.f ? v : expm1f(v);
}

// ---------------- launch ----------------
extern "C" void kernel_launch(void* const* d_in, const int* in_sizes, int n_in,
                              void* d_out, int out_size) {
    const int*   fea    = (const int*)  d_in[0];
    const int*   adj    = (const int*)  d_in[1];
    const float* mask   = (const float*)d_in[2];
    const float* embed  = (const float*)d_in[3];
    const float* Wheads = (const float*)d_in[4];
    const float* aheads = (const float*)d_in[5];
    const float* Wout   = (const float*)d_in[6];
    const float* aout   = (const float*)d_in[7];
    float* out = (float*)d_out;

    float *px, *pWh, *pe1, *pe2, *pattn, *phHB, *ph1, *pWh2, *pe1b, *pe2b, *pattn2, *ptmp;
    cudaGetSymbolAddress((void**)&px,     g_x);
    cudaGetSymbolAddress((void**)&pWh,    g_Wh);
    cudaGetSymbolAddress((void**)&pe1,    g_e1);
    cudaGetSymbolAddress((void**)&pe2,    g_e2);
    cudaGetSymbolAddress((void**)&pattn,  g_attn);
    cudaGetSymbolAddress((void**)&phHB,   g_hHB);
    cudaGetSymbolAddress((void**)&ph1,    g_h1);
    cudaGetSymbolAddress((void**)&pWh2,   g_Wh2);
    cudaGetSymbolAddress((void**)&pe1b,   g_e1b);
    cudaGetSymbolAddress((void**)&pe2b,   g_e2b);
    cudaGetSymbolAddress((void**)&pattn2, g_attn2);
    cudaGetSymbolAddress((void**)&ptmp,   g_tmp);

    // 1) embedding gather: x = embed[fea]
    gather_kernel<<<(cB * cN * cF + 255) / 256, 256>>>(fea, embed);

    // 2) Wh = x @ W_heads[h]   -> (H,B,N,O)
    gemm_kernel<<<dim3(cO / 64, (cB * cN) / 64, cH), 256>>>(
        px, Wheads, pWh, cB * cN, cO, cF,
        0LL, (long long)cF * cO, (long long)cB * cN * cO);

    // 3) e1/e2 per (h,b,n)
    attn_coef_kernel<<<(cH * cB * cN * 32 + 255) / 256, 256>>>(
        pWh, aheads, pe1, pe2, cO, cB * cN, cH * cB * cN);

    // 4) masked leaky softmax -> attn (H,B,N,N)
    softmax_kernel<<<cH * cB * cN, 256>>>(pe1, pe2, adj, pattn);

    // 5) hHB = attn @ Wh  (batched over H*B)
    gemm_kernel<<<dim3(cO / 64, cN / 64, cH * cB), 256>>>(
        pattn, pWh, phHB, cN, cO, cN,
        (long long)cN * cN, (long long)cN * cO, (long long)cN * cO);

    // 6) elu + head-concat transpose + mask -> h1 (B,N,H*O)
    head_merge_kernel<<<(cH * cB * cN * cO + 255) / 256, 256>>>(mask);

    // 7) Wh2 = h1 @ W_out  -> (B,N,OUT)
    gemm_kernel<<<dim3(cOUT / 64, (cB * cN) / 64, 1), 256>>>(
        ph1, Wout, pWh2, cB * cN, cOUT, cHO, 0LL, 0LL, 0LL);

    // 8) e1b/e2b per (b,n)
    attn_coef_kernel<<<(cB * cN * 32 + 255) / 256, 256>>>(
        pWh2, aout, pe1b, pe2b, cOUT, cB * cN, cB * cN);

    // 9) softmax -> attn2 (B,N,N)
    softmax_kernel<<<cB * cN, 256>>>(pe1b, pe2b, adj, pattn2);

    // 10) tmp = attn2 @ Wh2 (batched over B)
    gemm_kernel<<<dim3(cOUT / 64, cN / 64, cB), 256>>>(
        pattn2, pWh2, ptmp, cN, cOUT, cN,
        (long long)cN * cN, (long long)cN * cOUT, (long long)cN * cOUT);

    // 11) out = elu(tmp * mask)
    final_elu_kernel<<<(cB * cN * cOUT + 255) / 256, 256>>>(mask, out);
}

// round 2
// speedup vs baseline: 1.0019x; 1.0019x over previous
#include <cuda_runtime.h>
#include <math.h>

// Problem constants
constexpr int cB   = 32;
constexpr int cN   = 256;
constexpr int cF   = 300;
constexpr int cO   = 256;
constexpr int cH   = 8;
constexpr int cHO  = 2048;   // H*O
constexpr int cOUT = 512;
#define NEGV (-9e15f)

// ---------------- scratch (device globals; no allocation) ----------------
__device__ float g_x    [cB * cN * cF];                 // (B*N, F)
__device__ float g_Wh   [(size_t)cH * cB * cN * cO];    // (H,B,N,O)
__device__ float g_e1   [cH * cB * cN];
__device__ float g_e2   [cH * cB * cN];
__device__ float g_attn [(size_t)cH * cB * cN * cN];    // (H,B,N,N)
__device__ float g_hHB  [(size_t)cH * cB * cN * cO];    // (H,B,N,O)
__device__ float g_h1   [(size_t)cB * cN * cHO];        // (B,N,H*O)
__device__ float g_Wh2  [(size_t)cB * cN * cOUT];       // (B,N,OUT)
__device__ float g_e1b  [cB * cN];
__device__ float g_e2b  [cB * cN];
__device__ float g_attn2[(size_t)cB * cN * cN];         // (B,N,N)
__device__ float g_tmp  [(size_t)cB * cN * cOUT];       // pre-ELU output

// ---------------- embedding gather ----------------
__global__ void gather_kernel(const int* __restrict__ fea,
                              const float* __restrict__ embed) {
    int i = blockIdx.x * blockDim.x + threadIdx.x;
    if (i >= cB * cN * cF) return;
    int f  = i % cF;
    int bn = i / cF;
    g_x[i] = embed[(size_t)fea[bn] * cF + f];
}

// ---------------- generic batched GEMM: C = A @ B ----------------
// A: (M,K) row-major, B: (K,Nc) row-major, C: (M,Nc) row-major
// 64x64 block tile, K-tile 16, 256 threads, 4x4 microtile per thread.
__global__ __launch_bounds__(256)
void gemm_kernel(const float* __restrict__ A, const float* __restrict__ Bm,
                 float* __restrict__ C,
                 int M, int Nc, int K,
                 long long sA, long long sB, long long sC) {
    constexpr int BM = 64, BN = 64, BK = 16;
    __shared__ float As[BK][BM + 1];  // +1 pad: conflict-free transposed store
    __shared__ float Bs[BK][BN];

    int batch = blockIdx.z;
    A  += (long long)batch * sA;
    Bm += (long long)batch * sB;
    C  += (long long)batch * sC;

    int m0 = blockIdx.y * BM;
    int n0 = blockIdx.x * BN;
    int t  = threadIdx.x;
    int ty = t >> 4;          // 0..15
    int tx = t & 15;          // 0..15

    float acc[4][4] = {};

    for (int k0 = 0; k0 < K; k0 += BK) {
        // load A tile (64x16) transposed into As
        #pragma unroll
        for (int i = 0; i < 4; i++) {
            int idx = t + i * 256;
            int r = idx >> 4, c = idx & 15;
            float v = 0.f;
            if (k0 + c < K) v = A[(long long)(m0 + r) * K + (k0 + c)];
            As[c][r] = v;
        }
        // load B tile (16x64)
        #pragma unroll
        for (int i = 0; i < 4; i++) {
            int idx = t + i * 256;
            int r = idx >> 6, c = idx & 63;
            float v = 0.f;
            if (k0 + r < K) v = Bm[(long long)(k0 + r) * Nc + (n0 + c)];
            Bs[r][c] = v;
        }
        __syncthreads();

        #pragma unroll
        for (int kk = 0; kk < BK; kk++) {
            float a[4], b[4];
            #pragma unroll
            for (int i = 0; i < 4; i++) a[i] = As[kk][ty * 4 + i];
            #pragma unroll
            for (int j = 0; j < 4; j++) b[j] = Bs[kk][tx * 4 + j];
            #pragma unroll
            for (int i = 0; i < 4; i++)
                #pragma unroll
                for (int j = 0; j < 4; j++)
                    acc[i][j] = fmaf(a[i], b[j], acc[i][j]);
        }
        __syncthreads();
    }

    #pragma unroll
    for (int i = 0; i < 4; i++)
        #pragma unroll
        for (int j = 0; j < 4; j++)
            C[(long long)(m0 + ty * 4 + i) * Nc + (n0 + tx * 4 + j)] = acc[i][j];
}

// ---------------- attention coefficients: e1/e2 dot products ----------------
// One warp per row. Wh row length = Of. head = row / rowsPerHead; a: (heads, 2*Of)
__global__ void attn_coef_kernel(const float* __restrict__ Wh,
                                 const float* __restrict__ a,
                                 float* __restrict__ e1, float* __restrict__ e2,
                                 int Of, int rowsPerHead, int totalRows) {
    int gw = (blockIdx.x * blockDim.x + threadIdx.x) >> 5;
    if (gw >= totalRows) return;
    int lane = threadIdx.x & 31;
    int h = gw / rowsPerHead;
    const float* w  = Wh + (size_t)gw * Of;
    const float* a1 = a + (size_t)h * 2 * Of;
    const float* a2 = a1 + Of;
    float s1 = 0.f, s2 = 0.f;
    for (int o = lane; o < Of; o += 32) {
        float v = w[o];
        s1 = fmaf(v, a1[o], s1);
        s2 = fmaf(v, a2[o], s2);
    }
    #pragma unroll
    for (int off = 16; off; off >>= 1) {
        s1 += __shfl_xor_sync(0xffffffffu, s1, off);
        s2 += __shfl_xor_sync(0xffffffffu, s2, off);
    }
    if (lane == 0) { e1[gw] = s1; e2[gw] = s2; }
}

// ---------------- masked leaky-relu softmax over a row of N=256 ----------------
// One block (256 threads) per row r. Row layout: (H,B,N) (or (B,N) with H=1).
// adj is (B,N,N): b = (r/cN) % cB, n = r % cN.
__global__ void softmax_kernel(const float* __restrict__ e1,
                               const float* __restrict__ e2,
                               const int* __restrict__ adj,
                               float* __restrict__ attn) {
    int r  = blockIdx.x;
    int m  = threadIdx.x;
    int hb = r / cN;
    int n  = r - hb * cN;
    int b  = hb % cB;

    float v = e1[r] + e2[(size_t)hb * cN + m];
    v = v > 0.f ? v : 0.2f * v;                       // leaky relu
    if (adj[((size_t)b * cN + n) * cN + m] <= 0) v = NEGV;

    __shared__ float red[32];
    // --- block max ---
    float t = v;
    #pragma unroll
    for (int off = 16; off; off >>= 1) t = fmaxf(t, __shfl_xor_sync(0xffffffffu, t, off));
    if ((m & 31) == 0) red[m >> 5] = t;
    __syncthreads();
    if (m < 32) {
        float q = (m < 8) ? red[m] : -INFINITY;
        #pragma unroll
        for (int off = 4; off; off >>= 1) q = fmaxf(q, __shfl_xor_sync(0xffffffffu, q, off));
        if (m == 0) red[0] = q;
    }
    __syncthreads();
    float vmax = red[0];

    float ex = expf(v - vmax);

    __syncthreads();
    // --- block sum ---
    t = ex;
    #pragma unroll
    for (int off = 16; off; off >>= 1) t += __shfl_xor_sync(0xffffffffu, t, off);
    if ((m & 31) == 0) red[m >> 5] = t;
    __syncthreads();
    if (m < 32) {
        float q = (m < 8) ? red[m] : 0.f;
        #pragma unroll
        for (int off = 4; off; off >>= 1) q += __shfl_xor_sync(0xffffffffu, q, off);
        if (m == 0) red[0] = q;
    }
    __syncthreads();

    attn[(size_t)r * cN + m] = ex / red[0];
}

// ---------------- head merge: elu + transpose (H,B,N,O)->(B,N,H*O) + mask ----------------
__global__ void head_merge_kernel(const float* __restrict__ mask) {
    int i = blockIdx.x * blockDim.x + threadIdx.x;
    if (i >= cH * cB * cN * cO) return;
    int o   = i & (cO - 1);
    int rem = i >> 8;             // /cO
    int n   = rem & (cN - 1); rem >>= 8;
    int b   = rem & (cB - 1);
    int h   = rem >> 5;           // /cB
    float v = g_hHB[i];
    v = v > 0.f ? v : expm1f(v);  // ELU
    g_h1[((size_t)(b * cN + n)) * cHO + h * cO + o] = v * mask[b * cN + n];
}

// ---------------- final: out = elu(tmp * mask) ----------------
__global__ void final_elu_kernel(const float* __restrict__ mask,
                                 float* __restrict__ out) {
    int i = blockIdx.x * blockDim.x + threadIdx.x;
    if (i >= cB * cN * cOUT) return;
    float v = g_tmp[i] * mask[i / cOUT];
    out[i] = v > 0.f ? v : expm1f(v);
}

// ---------------- launch ----------------
extern "C" void kernel_launch(void* const* d_in, const int* in_sizes, int n_in,
                              void* d_out, int out_size) {
    const int*   fea    = (const int*)  d_in[0];
    const int*   adj    = (const int*)  d_in[1];
    const float* mask   = (const float*)d_in[2];
    const float* embed  = (const float*)d_in[3];
    const float* Wheads = (const float*)d_in[4];
    const float* aheads = (const float*)d_in[5];
    const float* Wout   = (const float*)d_in[6];
    const float* aout   = (const float*)d_in[7];
    float* out = (float*)d_out;

    float *px, *pWh, *pe1, *pe2, *pattn, *phHB, *ph1, *pWh2, *pe1b, *pe2b, *pattn2, *ptmp;
    cudaGetSymbolAddress((void**)&px,     g_x);
    cudaGetSymbolAddress((void**)&pWh,    g_Wh);
    cudaGetSymbolAddress((void**)&pe1,    g_e1);
    cudaGetSymbolAddress((void**)&pe2,    g_e2);
    cudaGetSymbolAddress((void**)&pattn,  g_attn);
    cudaGetSymbolAddress((void**)&phHB,   g_hHB);
    cudaGetSymbolAddress((void**)&ph1,    g_h1);
    cudaGetSymbolAddress((void**)&pWh2,   g_Wh2);
    cudaGetSymbolAddress((void**)&pe1b,   g_e1b);
    cudaGetSymbolAddress((void**)&pe2b,   g_e2b);
    cudaGetSymbolAddress((void**)&pattn2, g_attn2);
    cudaGetSymbolAddress((void**)&ptmp,   g_tmp);

    // 1) embedding gather: x = embed[fea]
    gather_kernel<<<(cB * cN * cF + 255) / 256, 256>>>(fea, embed);

    // 2) Wh = x @ W_heads[h]   -> (H,B,N,O)
    gemm_kernel<<<dim3(cO / 64, (cB * cN) / 64, cH), 256>>>(
        px, Wheads, pWh, cB * cN, cO, cF,
        0LL, (long long)cF * cO, (long long)cB * cN * cO);

    // 3) e1/e2 per (h,b,n)
    attn_coef_kernel<<<(cH * cB * cN * 32 + 255) / 256, 256>>>(
        pWh, aheads, pe1, pe2, cO, cB * cN, cH * cB * cN);

    // 4) masked leaky softmax -> attn (H,B,N,N)
    softmax_kernel<<<cH * cB * cN, 256>>>(pe1, pe2, adj, pattn);

    // 5) hHB = attn @ Wh  (batched over H*B)
    gemm_kernel<<<dim3(cO / 64, cN / 64, cH * cB), 256>>>(
        pattn, pWh, phHB, cN, cO, cN,
        (long long)cN * cN, (long long)cN * cO, (long long)cN * cO);

    // 6) elu + head-concat transpose + mask -> h1 (B,N,H*O)
    head_merge_kernel<<<(cH * cB * cN * cO + 255) / 256, 256>>>(mask);

    // 7) Wh2 = h1 @ W_out  -> (B,N,OUT)
    gemm_kernel<<<dim3(cOUT / 64, (cB * cN) / 64, 1), 256>>>(
        ph1, Wout, pWh2, cB * cN, cOUT, cHO, 0LL, 0LL, 0LL);

    // 8) e1b/e2b per (b,n)
    attn_coef_kernel<<<(cB * cN * 32 + 255) / 256, 256>>>(
        pWh2, aout, pe1b, pe2b, cOUT, cB * cN, cB * cN);

    // 9) softmax -> attn2 (B,N,N)
    softmax_kernel<<<cB * cN, 256>>>(pe1b, pe2b, adj, pattn2);

    // 10) tmp = attn2 @ Wh2 (batched over B)
    gemm_kernel<<<dim3(cOUT / 64, cN / 64, cB), 256>>>(
        pattn2, pWh2, ptmp, cN, cOUT, cN,
        (long long)cN * cN, (long long)cN * cOUT, (long long)cN * cOUT);

    // 11) out = elu(tmp * mask)
    final_elu_kernel<<<(cB * cN * cOUT + 255) / 256, 256>>>(mask, out);
}